// round 4
// baseline (speedup 1.0000x reference)
#include <cuda_runtime.h>
#include <cuda_bf16.h>

#define BATCH 4
#define SQL   2048
#define SKL   2048
#define EDIM  1024
#define NH    16
#define HDIM  64

// Scratch for projected Q/K/V (fp32), layout [B*H][S][64]
__device__ float g_Q[(size_t)BATCH * NH * SQL * HDIM];
__device__ float g_K[(size_t)BATCH * NH * SKL * HDIM];
__device__ float g_V[(size_t)BATCH * NH * SKL * HDIM];

// round-to-nearest fp32 -> tf32 (unbiased)
__device__ __forceinline__ unsigned f2tf(float f) {
    unsigned u;
    asm("cvt.rna.tf32.f32 %0, %1;" : "=r"(u) : "f"(f));
    return u;
}

__device__ __forceinline__ void mma_tf32(float* d, const unsigned* a, unsigned b0, unsigned b1) {
    asm volatile(
        "mma.sync.aligned.m16n8k8.row.col.f32.tf32.tf32.f32 "
        "{%0,%1,%2,%3}, {%4,%5,%6,%7}, {%8,%9}, {%0,%1,%2,%3};"
        : "+f"(d[0]), "+f"(d[1]), "+f"(d[2]), "+f"(d[3])
        : "r"(a[0]), "r"(a[1]), "r"(a[2]), "r"(a[3]), "r"(b0), "r"(b1));
}

// ---------------------------------------------------------------------------
// Projection: Out[bh][s][d] = sum_e X[b][s][e] * W[h][e][d]
// grid (SQL/128, B*H), block 256 (8 warps, 4x2 warp grid, warp tile 32x32)
// Tiles: BM=128(s) x BN=64(d) x BK=64(e).
// A = Xs[s][e] (row-major). B = Ws[e][d] (natural layout, NO transpose):
// B-frag b0 = B[k0+t][col+g], b1 = B[k0+t+4][col+g] read directly.
// ---------------------------------------------------------------------------
#define PBK 64
#define PST 68   // smem row stride (floats)

template <int WHICH>
__global__ __launch_bounds__(256) void proj_mma(const float* __restrict__ X,
                                                const float* __restrict__ W) {
    extern __shared__ unsigned psm[];
    unsigned* Xs = psm;                 // [128][PST]  tf32, [s][e]
    unsigned* Ws = psm + 128 * PST;     // [64][PST]   tf32, [e][d]

    float* Out = (WHICH == 0) ? g_Q : (WHICH == 1) ? g_K : g_V;

    const int bh = blockIdx.y;
    const int b  = bh >> 4;
    const int h  = bh & 15;
    const int s0 = blockIdx.x * 128;

    const float* Xb = X + ((size_t)b * SQL + s0) * EDIM;
    const float* Wh = W + (size_t)h * EDIM * HDIM;
    float*       Ob = Out + ((size_t)bh * SQL + s0) * HDIM;

    const int tid  = threadIdx.x;
    const int warp = tid >> 5;
    const int lane = tid & 31;
    const int g    = lane >> 2;   // groupID
    const int t    = lane & 3;    // thread-in-group
    const int wm   = warp >> 1;   // 0..3 -> 32 rows each
    const int wn   = warp & 1;    // 0..1 -> 32 cols each

    float acc[2][4][4];
#pragma unroll
    for (int mt = 0; mt < 2; mt++)
#pragma unroll
        for (int nt = 0; nt < 4; nt++)
#pragma unroll
            for (int r = 0; r < 4; r++) acc[mt][nt][r] = 0.f;

    for (int e0 = 0; e0 < EDIM; e0 += PBK) {
        // X tile 128x64 -> Xs (tf32), float4 loads, coalesced
#pragma unroll
        for (int it = 0; it < 8; it++) {
            int idx = tid + it * 256;          // 0..2047 float4
            int r   = idx >> 4;                // 0..127
            int c   = idx & 15;                // 0..15
            float4 v = *(const float4*)(Xb + (size_t)r * EDIM + e0 + c * 4);
            uint4 u = make_uint4(f2tf(v.x), f2tf(v.y), f2tf(v.z), f2tf(v.w));
            *(uint4*)&Xs[r * PST + c * 4] = u;
        }
        // W tile 64x64 -> Ws[e][d], float4 loads, coalesced (no transpose)
#pragma unroll
        for (int it = 0; it < 4; it++) {
            int idx = tid + it * 256;          // 0..1023 float4
            int r   = idx >> 4;                // 0..63 (e)
            int c   = idx & 15;                // 0..15
            float4 v = *(const float4*)(Wh + (size_t)(e0 + r) * HDIM + c * 4);
            uint4 u = make_uint4(f2tf(v.x), f2tf(v.y), f2tf(v.z), f2tf(v.w));
            *(uint4*)&Ws[r * PST + c * 4] = u;
        }
        __syncthreads();

#pragma unroll
        for (int ks = 0; ks < 8; ks++) {
            int k0 = ks * 8;
            unsigned a[2][4];
#pragma unroll
            for (int mt = 0; mt < 2; mt++) {
                int row = wm * 32 + mt * 16;
                a[mt][0] = Xs[(row + g) * PST + k0 + t];
                a[mt][1] = Xs[(row + 8 + g) * PST + k0 + t];
                a[mt][2] = Xs[(row + g) * PST + k0 + t + 4];
                a[mt][3] = Xs[(row + 8 + g) * PST + k0 + t + 4];
            }
#pragma unroll
            for (int nt = 0; nt < 4; nt++) {
                int col = wn * 32 + nt * 8;
                unsigned b0 = Ws[(k0 + t) * PST + col + g];
                unsigned b1 = Ws[(k0 + t + 4) * PST + col + g];
#pragma unroll
                for (int mt = 0; mt < 2; mt++) mma_tf32(acc[mt][nt], a[mt], b0, b1);
            }
        }
        __syncthreads();
    }

#pragma unroll
    for (int mt = 0; mt < 2; mt++) {
        int row = wm * 32 + mt * 16;
#pragma unroll
        for (int nt = 0; nt < 4; nt++) {
            int col = wn * 32 + nt * 8 + 2 * t;
            *(float2*)&Ob[(size_t)(row + g) * HDIM + col] =
                make_float2(acc[mt][nt][0], acc[mt][nt][1]);
            *(float2*)&Ob[(size_t)(row + 8 + g) * HDIM + col] =
                make_float2(acc[mt][nt][2], acc[mt][nt][3]);
        }
    }
}

// ---------------------------------------------------------------------------
// Flash attention, tf32 mma. grid (SQL/128, B*H), block 256 (8 warps).
// Each warp owns 16 q-rows x full 64 kv x full 64 d (softmax warp-local).
// smem: QPs[128][68] (Q frags preloaded to regs, buffer reused for P),
//       Ks[64][68] ([k][d]), Vs[64][68] ([k][d], NO transpose).
// PV B-frags read directly from Vs: b0 = Vs[(k0+t)][n+g], b1 = Vs[(k0+t+4)][n+g].
// ---------------------------------------------------------------------------
#define AST 68

__global__ __launch_bounds__(256) void attn_mma(float* __restrict__ out) {
    extern __shared__ unsigned asm_[];
    unsigned* QPs = asm_;                  // [128][AST]
    unsigned* Ks  = asm_ + 128 * AST;      // [64][AST]
    unsigned* Vs  = Ks + 64 * AST;         // [64][AST]

    const int bh = blockIdx.y;
    const int b  = bh >> 4;
    const int h  = bh & 15;
    const int q0 = blockIdx.x * 128;

    const float* Qb = g_Q + ((size_t)bh * SQL + q0) * HDIM;
    const float* Kb = g_K + (size_t)bh * SKL * HDIM;
    const float* Vb = g_V + (size_t)bh * SKL * HDIM;

    const int tid  = threadIdx.x;
    const int warp = tid >> 5;
    const int lane = tid & 31;
    const int g    = lane >> 2;
    const int t    = lane & 3;
    const int m0   = warp * 16;

    // Load Q tile (pre-scaled by 1/sqrt(64)) into smem as tf32
#pragma unroll
    for (int it = 0; it < 8; it++) {
        int idx = tid + it * 256;          // 0..2047 float4
        int r   = idx >> 4;
        int c   = idx & 15;
        float4 v = *(const float4*)(Qb + (size_t)r * HDIM + c * 4);
        uint4 u = make_uint4(f2tf(v.x * 0.125f), f2tf(v.y * 0.125f),
                             f2tf(v.z * 0.125f), f2tf(v.w * 0.125f));
        *(uint4*)&QPs[r * AST + c * 4] = u;
    }
    __syncthreads();

    // Preload Q fragments for all 8 k-steps (Q smem becomes P buffer after)
    unsigned qf[8][4];
#pragma unroll
    for (int ks = 0; ks < 8; ks++) {
        int k0 = ks * 8;
        qf[ks][0] = QPs[(m0 + g) * AST + k0 + t];
        qf[ks][1] = QPs[(m0 + 8 + g) * AST + k0 + t];
        qf[ks][2] = QPs[(m0 + g) * AST + k0 + t + 4];
        qf[ks][3] = QPs[(m0 + 8 + g) * AST + k0 + t + 4];
    }

    float Of[8][4];
#pragma unroll
    for (int nt = 0; nt < 8; nt++)
#pragma unroll
        for (int r = 0; r < 4; r++) Of[nt][r] = 0.f;
    float mr0 = -1e30f, mr1 = -1e30f, lr0 = 0.f, lr1 = 0.f;

    for (int kt = 0; kt < SKL / 64; kt++) {
        __syncthreads();  // prev iter's Ks/Vs reads done (and Q preload on iter 0)

        const float* Kt = Kb + (size_t)kt * 64 * HDIM;
        const float* Vp = Vb + (size_t)kt * 64 * HDIM;
        // K and V tiles [k][d] -> smem, float4, coalesced, no transpose
#pragma unroll
        for (int it = 0; it < 4; it++) {
            int idx = tid + it * 256;      // 0..1023 float4
            int r   = idx >> 4;
            int c   = idx & 15;
            float4 kv = *(const float4*)(Kt + (size_t)r * HDIM + c * 4);
            *(uint4*)&Ks[r * AST + c * 4] =
                make_uint4(f2tf(kv.x), f2tf(kv.y), f2tf(kv.z), f2tf(kv.w));
            float4 vv = *(const float4*)(Vp + (size_t)r * HDIM + c * 4);
            *(uint4*)&Vs[r * AST + c * 4] =
                make_uint4(f2tf(vv.x), f2tf(vv.y), f2tf(vv.z), f2tf(vv.w));
        }
        __syncthreads();

        // S = (Q*scale) @ K^T : B[k=d][n=kv] -> b0 = K[n+g][k0+t]
        float sf[8][4];
#pragma unroll
        for (int nt = 0; nt < 8; nt++)
#pragma unroll
            for (int r = 0; r < 4; r++) sf[nt][r] = 0.f;
#pragma unroll
        for (int ks = 0; ks < 8; ks++) {
            int k0 = ks * 8;
#pragma unroll
            for (int nt = 0; nt < 8; nt++) {
                unsigned b0 = Ks[(nt * 8 + g) * AST + k0 + t];
                unsigned b1 = Ks[(nt * 8 + g) * AST + k0 + t + 4];
                mma_tf32(sf[nt], qf[ks], b0, b1);
            }
        }

        // Online softmax. Row r0 = m0+g (regs 0,1), row r1 = m0+8+g (regs 2,3).
        float mx0 = -1e30f, mx1 = -1e30f;
#pragma unroll
        for (int nt = 0; nt < 8; nt++) {
            mx0 = fmaxf(mx0, fmaxf(sf[nt][0], sf[nt][1]));
            mx1 = fmaxf(mx1, fmaxf(sf[nt][2], sf[nt][3]));
        }
        mx0 = fmaxf(mx0, __shfl_xor_sync(0xffffffffu, mx0, 1));
        mx0 = fmaxf(mx0, __shfl_xor_sync(0xffffffffu, mx0, 2));
        mx1 = fmaxf(mx1, __shfl_xor_sync(0xffffffffu, mx1, 1));
        mx1 = fmaxf(mx1, __shfl_xor_sync(0xffffffffu, mx1, 2));
        float mn0 = fmaxf(mr0, mx0), mn1 = fmaxf(mr1, mx1);
        float al0 = __expf(mr0 - mn0), al1 = __expf(mr1 - mn1);
        mr0 = mn0; mr1 = mn1;
        float sum0 = 0.f, sum1 = 0.f;
#pragma unroll
        for (int nt = 0; nt < 8; nt++) {
            sf[nt][0] = __expf(sf[nt][0] - mn0); sum0 += sf[nt][0];
            sf[nt][1] = __expf(sf[nt][1] - mn0); sum0 += sf[nt][1];
            sf[nt][2] = __expf(sf[nt][2] - mn1); sum1 += sf[nt][2];
            sf[nt][3] = __expf(sf[nt][3] - mn1); sum1 += sf[nt][3];
        }
        sum0 += __shfl_xor_sync(0xffffffffu, sum0, 1);
        sum0 += __shfl_xor_sync(0xffffffffu, sum0, 2);
        sum1 += __shfl_xor_sync(0xffffffffu, sum1, 1);
        sum1 += __shfl_xor_sync(0xffffffffu, sum1, 2);
        lr0 = lr0 * al0 + sum0;
        lr1 = lr1 * al1 + sum1;
#pragma unroll
        for (int nt = 0; nt < 8; nt++) {
            Of[nt][0] *= al0; Of[nt][1] *= al0;
            Of[nt][2] *= al1; Of[nt][3] *= al1;
        }

        // Write P (tf32) into this warp's own 16 rows of QPs.
        // PV only reads the warp's OWN rows -> warp-level sync suffices.
#pragma unroll
        for (int nt = 0; nt < 8; nt++) {
            int col = nt * 8 + 2 * t;
            *(uint2*)&QPs[(m0 + g) * AST + col] =
                make_uint2(f2tf(sf[nt][0]), f2tf(sf[nt][1]));
            *(uint2*)&QPs[(m0 + 8 + g) * AST + col] =
                make_uint2(f2tf(sf[nt][2]), f2tf(sf[nt][3]));
        }
        __syncwarp(0xffffffffu);

        // O += P @ V : A = P (own rows), B[k=kv][n=d] -> b0 = Vs[k0+t][n+g]
#pragma unroll
        for (int ks = 0; ks < 8; ks++) {
            int k0 = ks * 8;
            unsigned pa[4];
            pa[0] = QPs[(m0 + g) * AST + k0 + t];
            pa[1] = QPs[(m0 + 8 + g) * AST + k0 + t];
            pa[2] = QPs[(m0 + g) * AST + k0 + t + 4];
            pa[3] = QPs[(m0 + 8 + g) * AST + k0 + t + 4];
#pragma unroll
            for (int nt = 0; nt < 8; nt++) {
                unsigned b0 = Vs[(k0 + t) * AST + nt * 8 + g];
                unsigned b1 = Vs[(k0 + t + 4) * AST + nt * 8 + g];
                mma_tf32(Of[nt], pa, b0, b1);
            }
        }
    }

    // Epilogue: out[b][q][d*NH + h] = O / l
    float inv0 = 1.f / lr0, inv1 = 1.f / lr1;
    int q_0 = q0 + m0 + g;
    int q_1 = q_0 + 8;
#pragma unroll
    for (int nt = 0; nt < 8; nt++) {
        int d0 = nt * 8 + 2 * t;
        size_t base0 = (((size_t)b * SQL + q_0) * HDIM + d0) * NH + h;
        size_t base1 = (((size_t)b * SQL + q_1) * HDIM + d0) * NH + h;
        out[base0]      = Of[nt][0] * inv0;
        out[base0 + NH] = Of[nt][1] * inv0;
        out[base1]      = Of[nt][2] * inv1;
        out[base1 + NH] = Of[nt][3] * inv1;
    }
}

// ---------------------------------------------------------------------------
extern "C" void kernel_launch(void* const* d_in, const int* in_sizes, int n_in,
                              void* d_out, int out_size) {
    const float* q  = (const float*)d_in[0];
    const float* k  = (const float*)d_in[1];
    const float* v  = (const float*)d_in[2];
    const float* Wq = (const float*)d_in[3];
    const float* Wk = (const float*)d_in[4];
    const float* Wv = (const float*)d_in[5];
    float* out = (float*)d_out;

    const int psmem = (128 + 64) * PST * (int)sizeof(unsigned);  // 52224 B
    cudaFuncSetAttribute(proj_mma<0>, cudaFuncAttributeMaxDynamicSharedMemorySize, psmem);
    cudaFuncSetAttribute(proj_mma<1>, cudaFuncAttributeMaxDynamicSharedMemorySize, psmem);
    cudaFuncSetAttribute(proj_mma<2>, cudaFuncAttributeMaxDynamicSharedMemorySize, psmem);
    dim3 pgrid(SQL / 128, BATCH * NH);
    proj_mma<0><<<pgrid, 256, psmem>>>(q, Wq);
    proj_mma<1><<<pgrid, 256, psmem>>>(k, Wk);
    proj_mma<2><<<pgrid, 256, psmem>>>(v, Wv);

    const int asmem = (128 + 64 + 64) * AST * (int)sizeof(unsigned);  // 69632 B
    cudaFuncSetAttribute(attn_mma, cudaFuncAttributeMaxDynamicSharedMemorySize, asmem);
    dim3 agrid(SQL / 128, BATCH * NH);
    attn_mma<<<agrid, 256, asmem>>>(out);
}

// round 7
// speedup vs baseline: 1.1548x; 1.1548x over previous
#include <cuda_runtime.h>

#define BATCH 4
#define SQL   2048
#define SKL   2048
#define EDIM  1024
#define NH    16
#define HDIM  64
#define NKT   (SKL / 64)

// Scratch for projected Q/K/V, layout [B*H][S][64].
// Values are stored ALREADY tf32-rounded (cvt.rna applied in proj epilogue),
// so attention can cp.async the bits straight into smem for the tf32 mma.
__device__ float g_Q[(size_t)BATCH * NH * SQL * HDIM];
__device__ float g_K[(size_t)BATCH * NH * SKL * HDIM];
__device__ float g_V[(size_t)BATCH * NH * SKL * HDIM];

// round-to-nearest fp32 -> tf32 (unbiased)
__device__ __forceinline__ unsigned f2tf(float f) {
    unsigned u;
    asm("cvt.rna.tf32.f32 %0, %1;" : "=r"(u) : "f"(f));
    return u;
}

__device__ __forceinline__ void mma_tf32(float* d, const unsigned* a, unsigned b0, unsigned b1) {
    asm volatile(
        "mma.sync.aligned.m16n8k8.row.col.f32.tf32.tf32.f32 "
        "{%0,%1,%2,%3}, {%4,%5,%6,%7}, {%8,%9}, {%0,%1,%2,%3};"
        : "+f"(d[0]), "+f"(d[1]), "+f"(d[2]), "+f"(d[3])
        : "r"(a[0]), "r"(a[1]), "r"(a[2]), "r"(a[3]), "r"(b0), "r"(b1));
}

__device__ __forceinline__ void cp16(unsigned smem_addr, const void* gptr) {
    asm volatile("cp.async.ca.shared.global [%0], [%1], 16;"
                 :: "r"(smem_addr), "l"(gptr));
}
__device__ __forceinline__ void cp_commit() {
    asm volatile("cp.async.commit_group;");
}
template <int N>
__device__ __forceinline__ void cp_wait() {
    asm volatile("cp.async.wait_group %0;" :: "n"(N));
}

// ---------------------------------------------------------------------------
// Projection: Out[bh][s][d] = sum_e X[b][s][e] * W[h][e][d]
// grid (SQL/128, B*H), block 256 (8 warps, 4x2 warp grid, warp tile 32x32)
// A = Xs[s][e] row-major. B = Ws[e][d] natural layout (no transpose).
// Epilogue stores tf32-rounded values (numerically identical to rounding at
// the consumer, enables cp.async in attention).
// ---------------------------------------------------------------------------
#define PBK 64
#define PST 68   // smem row stride (floats)

template <int WHICH>
__global__ __launch_bounds__(256, 2) void proj_mma(const float* __restrict__ X,
                                                   const float* __restrict__ W) {
    extern __shared__ unsigned psm[];
    unsigned* Xs = psm;                 // [128][PST]  tf32, [s][e]
    unsigned* Ws = psm + 128 * PST;     // [64][PST]   tf32, [e][d]

    float* Out = (WHICH == 0) ? g_Q : (WHICH == 1) ? g_K : g_V;

    const int bh = blockIdx.y;
    const int b  = bh >> 4;
    const int h  = bh & 15;
    const int s0 = blockIdx.x * 128;

    const float* Xb = X + ((size_t)b * SQL + s0) * EDIM;
    const float* Wh = W + (size_t)h * EDIM * HDIM;
    float*       Ob = Out + ((size_t)bh * SQL + s0) * HDIM;

    const int tid  = threadIdx.x;
    const int warp = tid >> 5;
    const int lane = tid & 31;
    const int g    = lane >> 2;
    const int t    = lane & 3;
    const int wm   = warp >> 1;
    const int wn   = warp & 1;

    float acc[2][4][4];
#pragma unroll
    for (int mt = 0; mt < 2; mt++)
#pragma unroll
        for (int nt = 0; nt < 4; nt++)
#pragma unroll
            for (int r = 0; r < 4; r++) acc[mt][nt][r] = 0.f;

    for (int e0 = 0; e0 < EDIM; e0 += PBK) {
#pragma unroll
        for (int it = 0; it < 8; it++) {
            int idx = tid + it * 256;
            int r   = idx >> 4;
            int c   = idx & 15;
            float4 v = *(const float4*)(Xb + (size_t)r * EDIM + e0 + c * 4);
            *(uint4*)&Xs[r * PST + c * 4] =
                make_uint4(f2tf(v.x), f2tf(v.y), f2tf(v.z), f2tf(v.w));
        }
#pragma unroll
        for (int it = 0; it < 4; it++) {
            int idx = tid + it * 256;
            int r   = idx >> 4;
            int c   = idx & 15;
            float4 v = *(const float4*)(Wh + (size_t)(e0 + r) * HDIM + c * 4);
            *(uint4*)&Ws[r * PST + c * 4] =
                make_uint4(f2tf(v.x), f2tf(v.y), f2tf(v.z), f2tf(v.w));
        }
        __syncthreads();

#pragma unroll
        for (int ks = 0; ks < 8; ks++) {
            int k0 = ks * 8;
            unsigned a[2][4];
#pragma unroll
            for (int mt = 0; mt < 2; mt++) {
                int row = wm * 32 + mt * 16;
                a[mt][0] = Xs[(row + g) * PST + k0 + t];
                a[mt][1] = Xs[(row + 8 + g) * PST + k0 + t];
                a[mt][2] = Xs[(row + g) * PST + k0 + t + 4];
                a[mt][3] = Xs[(row + 8 + g) * PST + k0 + t + 4];
            }
#pragma unroll
            for (int nt = 0; nt < 4; nt++) {
                int col = wn * 32 + nt * 8;
                unsigned b0 = Ws[(k0 + t) * PST + col + g];
                unsigned b1 = Ws[(k0 + t + 4) * PST + col + g];
#pragma unroll
                for (int mt = 0; mt < 2; mt++) mma_tf32(acc[mt][nt], a[mt], b0, b1);
            }
        }
        __syncthreads();
    }

    // Store tf32-rounded outputs (bit pattern of cvt.rna result).
#pragma unroll
    for (int mt = 0; mt < 2; mt++) {
        int row = wm * 32 + mt * 16;
#pragma unroll
        for (int nt = 0; nt < 4; nt++) {
            int col = wn * 32 + nt * 8 + 2 * t;
            *(float2*)&Ob[(size_t)(row + g) * HDIM + col] =
                make_float2(__uint_as_float(f2tf(acc[mt][nt][0])),
                            __uint_as_float(f2tf(acc[mt][nt][1])));
            *(float2*)&Ob[(size_t)(row + 8 + g) * HDIM + col] =
                make_float2(__uint_as_float(f2tf(acc[mt][nt][2])),
                            __uint_as_float(f2tf(acc[mt][nt][3])));
        }
    }
}

// ---------------------------------------------------------------------------
// Flash attention, tf32 mma + cp.async double-buffered K/V pipeline.
// grid (SQL/128, B*H), block 256 (8 warps), 2 CTAs/SM.
// Warp owns 16 q-rows x 64 kv x 64 d (softmax warp-local).
// smem: QPs[128][AST] (Q frags preloaded to regs, buffer reused for P),
//       K2[2][64][AST], V2[2][64][AST] double buffers ([k][d], no transpose).
// ---------------------------------------------------------------------------
#define AST 68
#define TILEW (64 * AST)   // words per K or V tile

__global__ __launch_bounds__(256, 2) void attn_mma(float* __restrict__ out) {
    extern __shared__ unsigned asm_[];
    unsigned* QPs = asm_;                        // [128][AST]
    unsigned* K2  = asm_ + 128 * AST;            // [2][64][AST]
    unsigned* V2  = K2 + 2 * TILEW;              // [2][64][AST]

    const int bh = blockIdx.y;
    const int b  = bh >> 4;
    const int h  = bh & 15;
    const int q0 = blockIdx.x * 128;

    const float* Qb = g_Q + ((size_t)bh * SQL + q0) * HDIM;
    const float* Kb = g_K + (size_t)bh * SKL * HDIM;
    const float* Vb = g_V + (size_t)bh * SKL * HDIM;

    const int tid  = threadIdx.x;
    const int warp = tid >> 5;
    const int lane = tid & 31;
    const int g    = lane >> 2;
    const int t    = lane & 3;
    const int m0   = warp * 16;

    const unsigned sbase = (unsigned)__cvta_generic_to_shared(asm_);
    const unsigned sK    = sbase + 128 * AST * 4;
    const unsigned sV    = sK + 2 * TILEW * 4;

    // Per-thread cp.async chunk coordinates (4 x 16B per tile per array)
    // idx = tid + it*256; r = idx>>4; c = (idx&15)*4
    // Prefetch tile 0 into buffer 0 first (longest latency first).
    {
        const float* Kt = Kb;
        const float* Vp = Vb;
#pragma unroll
        for (int it = 0; it < 4; it++) {
            int idx = tid + it * 256;
            int r   = idx >> 4;
            int c   = (idx & 15) * 4;
            cp16(sK + (unsigned)(r * AST + c) * 4, Kt + (size_t)r * HDIM + c);
            cp16(sV + (unsigned)(r * AST + c) * 4, Vp + (size_t)r * HDIM + c);
        }
        cp_commit();
    }

    // Load Q tile (pre-rounded in gmem; *0.125 is exact) into smem
#pragma unroll
    for (int it = 0; it < 8; it++) {
        int idx = tid + it * 256;
        int r   = idx >> 4;
        int c   = idx & 15;
        float4 v = *(const float4*)(Qb + (size_t)r * HDIM + c * 4);
        *(uint4*)&QPs[r * AST + c * 4] =
            make_uint4(__float_as_uint(v.x * 0.125f), __float_as_uint(v.y * 0.125f),
                       __float_as_uint(v.z * 0.125f), __float_as_uint(v.w * 0.125f));
    }
    __syncthreads();

    // Preload Q fragments for all 8 k-steps (QPs becomes the P buffer after)
    unsigned qf[8][4];
#pragma unroll
    for (int ks = 0; ks < 8; ks++) {
        int k0 = ks * 8;
        qf[ks][0] = QPs[(m0 + g) * AST + k0 + t];
        qf[ks][1] = QPs[(m0 + 8 + g) * AST + k0 + t];
        qf[ks][2] = QPs[(m0 + g) * AST + k0 + t + 4];
        qf[ks][3] = QPs[(m0 + 8 + g) * AST + k0 + t + 4];
    }

    float Of[8][4];
#pragma unroll
    for (int nt = 0; nt < 8; nt++)
#pragma unroll
        for (int r = 0; r < 4; r++) Of[nt][r] = 0.f;
    float mr0 = -1e30f, mr1 = -1e30f, lr0 = 0.f, lr1 = 0.f;

    for (int kt = 0; kt < NKT; kt++) {
        const int cur = kt & 1;

        // Prefetch next tile into the other buffer (its readers finished at
        // the end-sync of iteration kt-1).
        if (kt + 1 < NKT) {
            const int nb = cur ^ 1;
            const float* Kt = Kb + (size_t)(kt + 1) * 64 * HDIM;
            const float* Vp = Vb + (size_t)(kt + 1) * 64 * HDIM;
#pragma unroll
            for (int it = 0; it < 4; it++) {
                int idx = tid + it * 256;
                int r   = idx >> 4;
                int c   = (idx & 15) * 4;
                cp16(sK + (unsigned)(nb * TILEW + r * AST + c) * 4,
                     Kt + (size_t)r * HDIM + c);
                cp16(sV + (unsigned)(nb * TILEW + r * AST + c) * 4,
                     Vp + (size_t)r * HDIM + c);
            }
            cp_commit();
            cp_wait<1>();   // tile kt complete; tile kt+1 may stay in flight
        } else {
            cp_wait<0>();   // drain the last tile
        }
        __syncthreads();    // tile kt visible to all warps

        const unsigned* Ks = K2 + cur * TILEW;
        const unsigned* Vs = V2 + cur * TILEW;

        // S = (Q*scale) @ K^T : b0 = K[n+g][k0+t]
        float sf[8][4];
#pragma unroll
        for (int nt = 0; nt < 8; nt++)
#pragma unroll
            for (int r = 0; r < 4; r++) sf[nt][r] = 0.f;
#pragma unroll
        for (int ks = 0; ks < 8; ks++) {
            int k0 = ks * 8;
#pragma unroll
            for (int nt = 0; nt < 8; nt++) {
                unsigned b0 = Ks[(nt * 8 + g) * AST + k0 + t];
                unsigned b1 = Ks[(nt * 8 + g) * AST + k0 + t + 4];
                mma_tf32(sf[nt], qf[ks], b0, b1);
            }
        }

        // Online softmax. Row r0 = m0+g (regs 0,1), row r1 = m0+8+g (regs 2,3).
        float mx0 = -1e30f, mx1 = -1e30f;
#pragma unroll
        for (int nt = 0; nt < 8; nt++) {
            mx0 = fmaxf(mx0, fmaxf(sf[nt][0], sf[nt][1]));
            mx1 = fmaxf(mx1, fmaxf(sf[nt][2], sf[nt][3]));
        }
        mx0 = fmaxf(mx0, __shfl_xor_sync(0xffffffffu, mx0, 1));
        mx0 = fmaxf(mx0, __shfl_xor_sync(0xffffffffu, mx0, 2));
        mx1 = fmaxf(mx1, __shfl_xor_sync(0xffffffffu, mx1, 1));
        mx1 = fmaxf(mx1, __shfl_xor_sync(0xffffffffu, mx1, 2));
        float mn0 = fmaxf(mr0, mx0), mn1 = fmaxf(mr1, mx1);
        float al0 = __expf(mr0 - mn0), al1 = __expf(mr1 - mn1);
        mr0 = mn0; mr1 = mn1;
        float sum0 = 0.f, sum1 = 0.f;
#pragma unroll
        for (int nt = 0; nt < 8; nt++) {
            sf[nt][0] = __expf(sf[nt][0] - mn0); sum0 += sf[nt][0];
            sf[nt][1] = __expf(sf[nt][1] - mn0); sum0 += sf[nt][1];
            sf[nt][2] = __expf(sf[nt][2] - mn1); sum1 += sf[nt][2];
            sf[nt][3] = __expf(sf[nt][3] - mn1); sum1 += sf[nt][3];
        }
        sum0 += __shfl_xor_sync(0xffffffffu, sum0, 1);
        sum0 += __shfl_xor_sync(0xffffffffu, sum0, 2);
        sum1 += __shfl_xor_sync(0xffffffffu, sum1, 1);
        sum1 += __shfl_xor_sync(0xffffffffu, sum1, 2);
        lr0 = lr0 * al0 + sum0;
        lr1 = lr1 * al1 + sum1;
#pragma unroll
        for (int nt = 0; nt < 8; nt++) {
            Of[nt][0] *= al0; Of[nt][1] *= al0;
            Of[nt][2] *= al1; Of[nt][3] *= al1;
        }

        // Write P (tf32) into this warp's own 16 rows of QPs (warp-local).
#pragma unroll
        for (int nt = 0; nt < 8; nt++) {
            int col = nt * 8 + 2 * t;
            *(uint2*)&QPs[(m0 + g) * AST + col] =
                make_uint2(f2tf(sf[nt][0]), f2tf(sf[nt][1]));
            *(uint2*)&QPs[(m0 + 8 + g) * AST + col] =
                make_uint2(f2tf(sf[nt][2]), f2tf(sf[nt][3]));
        }
        __syncwarp(0xffffffffu);

        // O += P @ V : A = P (own rows), b0 = Vs[k0+t][n+g]
#pragma unroll
        for (int ks = 0; ks < 8; ks++) {
            int k0 = ks * 8;
            unsigned pa[4];
            pa[0] = QPs[(m0 + g) * AST + k0 + t];
            pa[1] = QPs[(m0 + 8 + g) * AST + k0 + t];
            pa[2] = QPs[(m0 + g) * AST + k0 + t + 4];
            pa[3] = QPs[(m0 + 8 + g) * AST + k0 + t + 4];
#pragma unroll
            for (int nt = 0; nt < 8; nt++) {
                unsigned b0 = Vs[(k0 + t) * AST + nt * 8 + g];
                unsigned b1 = Vs[(k0 + t + 4) * AST + nt * 8 + g];
                mma_tf32(Of[nt], pa, b0, b1);
            }
        }
        __syncthreads();  // all reads of buffer `cur` done before it is refilled
    }

    // Epilogue: out[b][q][d*NH + h] = O / l
    float inv0 = 1.f / lr0, inv1 = 1.f / lr1;
    int q_0 = q0 + m0 + g;
    int q_1 = q_0 + 8;
#pragma unroll
    for (int nt = 0; nt < 8; nt++) {
        int d0 = nt * 8 + 2 * t;
        size_t base0 = (((size_t)b * SQL + q_0) * HDIM + d0) * NH + h;
        size_t base1 = (((size_t)b * SQL + q_1) * HDIM + d0) * NH + h;
        out[base0]      = Of[nt][0] * inv0;
        out[base0 + NH] = Of[nt][1] * inv0;
        out[base1]      = Of[nt][2] * inv1;
        out[base1 + NH] = Of[nt][3] * inv1;
    }
}

// ---------------------------------------------------------------------------
extern "C" void kernel_launch(void* const* d_in, const int* in_sizes, int n_in,
                              void* d_out, int out_size) {
    const float* q  = (const float*)d_in[0];
    const float* k  = (const float*)d_in[1];
    const float* v  = (const float*)d_in[2];
    const float* Wq = (const float*)d_in[3];
    const float* Wk = (const float*)d_in[4];
    const float* Wv = (const float*)d_in[5];
    float* out = (float*)d_out;

    const int psmem = (128 + 64) * PST * (int)sizeof(unsigned);  // 52224 B
    cudaFuncSetAttribute(proj_mma<0>, cudaFuncAttributeMaxDynamicSharedMemorySize, psmem);
    cudaFuncSetAttribute(proj_mma<1>, cudaFuncAttributeMaxDynamicSharedMemorySize, psmem);
    cudaFuncSetAttribute(proj_mma<2>, cudaFuncAttributeMaxDynamicSharedMemorySize, psmem);
    dim3 pgrid(SQL / 128, BATCH * NH);
    proj_mma<0><<<pgrid, 256, psmem>>>(q, Wq);
    proj_mma<1><<<pgrid, 256, psmem>>>(k, Wk);
    proj_mma<2><<<pgrid, 256, psmem>>>(v, Wv);

    // QPs + 2*(K+V) tiles = (128 + 4*64) * AST words = 104448 B
    const int asmem = (128 + 4 * 64) * AST * (int)sizeof(unsigned);
    cudaFuncSetAttribute(attn_mma, cudaFuncAttributeMaxDynamicSharedMemorySize, asmem);
    dim3 agrid(SQL / 128, BATCH * NH);
    attn_mma<<<agrid, 256, asmem>>>(out);
}